// round 1
// baseline (speedup 1.0000x reference)
#include <cuda_runtime.h>

#define BATCH 16
#define SPOS  1024
#define DIM   512
#define KC    12
#define KCTR  10
#define SC    8
#define SLEN  (SPOS / SC)   // 128

// Scratch (no allocations allowed): partial sums + partial softmax-sums
__device__ float g_partial[BATCH * SC * KCTR * DIM];   // 3.1 MB
__device__ float g_asum[BATCH * SC * KCTR];

__device__ __forceinline__ void fma2(unsigned long long& acc,
                                     unsigned long long a,
                                     unsigned long long f) {
    // packed fp32x2 FMA: acc = a * f + acc  (two lanes)
    asm("fma.rn.f32x2 %0, %1, %2, %0;" : "+l"(acc) : "l"(a), "l"(f));
}

__global__ __launch_bounds__(256, 1)
void vlad_k1(const float* __restrict__ feat, const float* __restrict__ score) {
    __shared__ __align__(16) unsigned long long Ash[SLEN][KCTR]; // {a,a} pairs, 10 KB
    __shared__ float asum_part[KCTR][8];

    const int tid = threadIdx.x;
    const int b = blockIdx.x / SC;
    const int c = blockIdx.x % SC;
    const int s0 = c * SLEN;

    // ---- Phase 1: softmax over KC=12, store duplicated pairs for k<10 ----
    if (tid < SLEN) {
        const float* sp = score + (size_t)(b * SPOS + s0 + tid) * KC;
        float v[KC];
        float m = -1e30f;
        #pragma unroll
        for (int k = 0; k < KC; k++) { v[k] = sp[k]; m = fmaxf(m, v[k]); }
        float sum = 0.f;
        #pragma unroll
        for (int k = 0; k < KC; k++) { v[k] = __expf(v[k] - m); sum += v[k]; }
        float inv = 1.f / sum;
        #pragma unroll
        for (int k = 0; k < KCTR; k++) {
            unsigned int u = __float_as_uint(v[k] * inv);
            Ash[tid][k] = ((unsigned long long)u << 32) | (unsigned long long)u;
        }
    }
    __syncthreads();

    // ---- Main loop: each thread owns 2 adjacent d; accumulate 10 centers ----
    const unsigned long long* fp =
        (const unsigned long long*)(feat + (size_t)(b * SPOS + s0) * DIM) + tid;

    unsigned long long acc[KCTR];
    #pragma unroll
    for (int k = 0; k < KCTR; k++) acc[k] = 0ull;   // bits of {0.f,0.f}

    #pragma unroll 4
    for (int s = 0; s < SLEN; s++) {
        unsigned long long f = fp[(size_t)s * (DIM / 2)];
        const ulonglong2* ar = (const ulonglong2*)Ash[s];  // 16B-aligned rows (80B stride)
        ulonglong2 a01 = ar[0], a23 = ar[1], a45 = ar[2], a67 = ar[3], a89 = ar[4];
        fma2(acc[0], a01.x, f); fma2(acc[1], a01.y, f);
        fma2(acc[2], a23.x, f); fma2(acc[3], a23.y, f);
        fma2(acc[4], a45.x, f); fma2(acc[5], a45.y, f);
        fma2(acc[6], a67.x, f); fma2(acc[7], a67.y, f);
        fma2(acc[8], a89.x, f); fma2(acc[9], a89.y, f);
    }

    // ---- Write partials ----
    unsigned long long* gp = (unsigned long long*)g_partial
                           + (size_t)(b * SC + c) * KCTR * (DIM / 2) + tid;
    #pragma unroll
    for (int k = 0; k < KCTR; k++) gp[(size_t)k * (DIM / 2)] = acc[k];

    // ---- Asum partials (column sums of A over this s-chunk), tree-reduced ----
    if (tid < KCTR * 8) {
        int k = tid >> 3, p = tid & 7;
        float ssum = 0.f;
        #pragma unroll
        for (int i = 0; i < SLEN / 8; i++)
            ssum += __uint_as_float((unsigned int)Ash[p * (SLEN / 8) + i][k]);
        asum_part[k][p] = ssum;
    }
    __syncthreads();
    if (tid < KCTR) {
        float t = 0.f;
        #pragma unroll
        for (int p = 0; p < 8; p++) t += asum_part[tid][p];
        g_asum[(b * SC + c) * KCTR + tid] = t;
    }
}

__global__ __launch_bounds__(128, 8)
void vlad_k2(const float* __restrict__ cluster, float* __restrict__ out) {
    const int tid = threadIdx.x;
    const int b = blockIdx.x / KCTR;
    const int k = blockIdx.x % KCTR;

    float4 r = make_float4(0.f, 0.f, 0.f, 0.f);
    const float4* pp = (const float4*)g_partial;
    #pragma unroll
    for (int c = 0; c < SC; c++) {
        float4 p = pp[((size_t)(b * SC + c) * KCTR + k) * (DIM / 4) + tid];
        r.x += p.x; r.y += p.y; r.z += p.z; r.w += p.w;
    }

    float asum = 0.f;
    #pragma unroll
    for (int c = 0; c < SC; c++) asum += g_asum[(b * SC + c) * KCTR + k];

    float4 cl = ((const float4*)cluster)[k * (DIM / 4) + tid];
    r.x -= asum * cl.x; r.y -= asum * cl.y;
    r.z -= asum * cl.z; r.w -= asum * cl.w;

    float sq = r.x * r.x + r.y * r.y + r.z * r.z + r.w * r.w;
    #pragma unroll
    for (int o = 16; o > 0; o >>= 1) sq += __shfl_xor_sync(0xffffffffu, sq, o);

    __shared__ float red[4];
    if ((tid & 31) == 0) red[tid >> 5] = sq;
    __syncthreads();
    float tot = red[0] + red[1] + red[2] + red[3];
    float inv = rsqrtf(fmaxf(tot, 1e-12f));

    float4 o4 = make_float4(r.x * inv, r.y * inv, r.z * inv, r.w * inv);
    ((float4*)out)[(size_t)(b * KCTR + k) * (DIM / 4) + tid] = o4;
}

extern "C" void kernel_launch(void* const* d_in, const int* in_sizes, int n_in,
                              void* d_out, int out_size) {
    const float* feat    = (const float*)d_in[0];  // (16,16,64,512) f32
    const float* score   = (const float*)d_in[1];  // (16,16,64,12)  f32
    const float* cluster = (const float*)d_in[2];  // (12,512)       f32
    float* out = (float*)d_out;                    // (16,5120)      f32

    vlad_k1<<<BATCH * SC, 256>>>(feat, score);
    vlad_k2<<<BATCH * KCTR, 128>>>(cluster, out);
}